// round 6
// baseline (speedup 1.0000x reference)
#include <cuda_runtime.h>
#include <cuda_bf16.h>
#include <math.h>

#define S   1024
#define B_  16
#define D_  768
#define H_  384
#define G3  1152   // 3*H
#define RNC 48     // CTAs per direction in recurrence
#define RJ  8      // h-columns per CTA (384/48)
#define RT  192    // threads per recurrence CTA

// ---------------- scratch (device globals; no allocation) ----------------
__device__ float         g_X [S*B_*D_];        // layer input,  (s*16+b, 768)
__device__ float         g_XG[2][S*B_*G3];     // gate proj, [dir][(s*16+b)*1152+g]
__device__ __nv_bfloat16 g_hbf[2][2][2][7680]; // [dir][phase][hi/lo][12 chunk][16 b][40]
__device__ int           g_flags[3][2][RNC];   // [layer][dir][cid] step-ready flags

// ---------------- patchify + flag reset ----------------
__global__ void patchify_k(const float* __restrict__ x) {
    unsigned gi = blockIdx.x * blockDim.x + threadIdx.x;
    if (gi < 3 * 2 * RNC) ((int*)g_flags)[gi] = 0;
    unsigned j  = gi & 511;
    unsigned i  = (gi >> 9) & 511;
    unsigned bc = gi >> 18;
    unsigned c  = bc % 3;
    unsigned b  = bc / 3;
    unsigned s  = (i >> 4) * 32 + (j >> 4);
    unsigned k  = (((i & 15) << 4) + (j & 15)) * 3 + c;
    g_X[(size_t)(s * 16 + b) * 768 + k] = x[gi];
}

// ================= shared bf16 split helpers =================
#define SMBLK 5120          // halfs per GEMM buffer block (128 rows * 40)
#define ROWH  40            // padded row length in halfs (80 bytes)

__device__ __forceinline__ void split8(const float* v, uint4& H, uint4& L) {
    unsigned h[4], l[4];
#pragma unroll
    for (int i = 0; i < 4; i++) {
        float a = v[2*i], b = v[2*i+1];
        __nv_bfloat16 ha = __float2bfloat16_rn(a), hb = __float2bfloat16_rn(b);
        float ra = a - __bfloat162float(ha), rb = b - __bfloat162float(hb);
        __nv_bfloat16 la = __float2bfloat16_rn(ra), lb = __float2bfloat16_rn(rb);
        h[i] = (unsigned)__bfloat16_as_ushort(ha) | ((unsigned)__bfloat16_as_ushort(hb) << 16);
        l[i] = (unsigned)__bfloat16_as_ushort(la) | ((unsigned)__bfloat16_as_ushort(lb) << 16);
    }
    H = make_uint4(h[0], h[1], h[2], h[3]);
    L = make_uint4(l[0], l[1], l[2], l[3]);
}

#define LDSM4(r, addr) \
    asm volatile("ldmatrix.sync.aligned.m8n8.x4.shared.b16 {%0,%1,%2,%3},[%4];" \
        : "=r"((r)[0]), "=r"((r)[1]), "=r"((r)[2]), "=r"((r)[3]) : "r"(addr))

#define MMA16816(d, a, b) \
    asm volatile("mma.sync.aligned.m16n8k16.row.col.f32.bf16.bf16.f32 " \
        "{%0,%1,%2,%3},{%4,%5,%6,%7},{%8,%9},{%0,%1,%2,%3};" \
        : "+f"((d)[0]), "+f"((d)[1]), "+f"((d)[2]), "+f"((d)[3]) \
        : "r"((a)[0]), "r"((a)[1]), "r"((a)[2]), "r"((a)[3]), "r"((b)[0]), "r"((b)[1]))

// ================= bf16 split-3 tensor-core GEMM (unchanged) =================
__global__ void __launch_bounds__(256, 1) gemm_xg_k(const float* __restrict__ Wih,
                                                    const float* __restrict__ bih) {
    extern __shared__ __nv_bfloat16 SM[];
    int tid  = threadIdx.x;
    int lane = tid & 31;
    int w    = tid >> 5;
    int m0   = blockIdx.y * 128;
    int n0   = blockIdx.x * 128;
    int bm   = (w >> 1) * 32;
    int bn   = (w & 1) * 64;

    int r  = tid >> 1;
    int c0 = (tid & 1) * 16;
    const float* Ag = g_X + (size_t)(m0 + r) * 768 + c0;
    const float* Bg = Wih + (size_t)(n0 + r) * 768 + c0;

    unsigned sbase = (unsigned)__cvta_generic_to_shared(SM);
    unsigned a_off = (unsigned)((bm + (lane & 15)) * 80 + ((lane >> 4) & 1) * 16);
    unsigned b_off = (unsigned)((bn + ((lane >> 4) & 1) * 8 + (lane & 7)) * 80 + ((lane >> 3) & 1) * 16);

    float c[2][8][4];
#pragma unroll
    for (int i = 0; i < 2; i++)
#pragma unroll
        for (int j = 0; j < 8; j++)
#pragma unroll
            for (int q = 0; q < 4; q++) c[i][j][q] = 0.f;

    float av[16], bv[16];
#pragma unroll
    for (int i = 0; i < 4; i++) {
        *(float4*)(av + 4*i) = *(const float4*)(Ag + 4*i);
        *(float4*)(bv + 4*i) = *(const float4*)(Bg + 4*i);
    }

    for (int kc = 0; kc < 24; kc++) {
        int buf = kc & 1;
        __nv_bfloat16* base = SM + buf * 4 * SMBLK;
        {
            uint4 H0, L0, H1, L1;
            split8(av,     H0, L0);
            split8(av + 8, H1, L1);
            *(uint4*)(base + 0*SMBLK + r*ROWH + c0)     = H0;
            *(uint4*)(base + 0*SMBLK + r*ROWH + c0 + 8) = H1;
            *(uint4*)(base + 1*SMBLK + r*ROWH + c0)     = L0;
            *(uint4*)(base + 1*SMBLK + r*ROWH + c0 + 8) = L1;
            split8(bv,     H0, L0);
            split8(bv + 8, H1, L1);
            *(uint4*)(base + 2*SMBLK + r*ROWH + c0)     = H0;
            *(uint4*)(base + 2*SMBLK + r*ROWH + c0 + 8) = H1;
            *(uint4*)(base + 3*SMBLK + r*ROWH + c0)     = L0;
            *(uint4*)(base + 3*SMBLK + r*ROWH + c0 + 8) = L1;
        }
        if (kc < 23) {
            const float* An = Ag + (kc + 1) * 32;
            const float* Bn = Bg + (kc + 1) * 32;
#pragma unroll
            for (int i = 0; i < 4; i++) {
                *(float4*)(av + 4*i) = *(const float4*)(An + 4*i);
                *(float4*)(bv + 4*i) = *(const float4*)(Bn + 4*i);
            }
        }
        __syncthreads();

        unsigned bb = sbase + (unsigned)(buf * 4 * SMBLK * 2);
#pragma unroll
        for (int kk = 0; kk < 2; kk++) {
            unsigned ah[2][4], al[2][4], bh[4][4], bl[4][4];
#pragma unroll
            for (int mt = 0; mt < 2; mt++) {
                LDSM4(ah[mt], bb + 0*SMBLK*2 + a_off + mt*1280 + kk*32);
                LDSM4(al[mt], bb + 1*SMBLK*2 + a_off + mt*1280 + kk*32);
            }
#pragma unroll
            for (int np = 0; np < 4; np++) {
                LDSM4(bh[np], bb + 2*SMBLK*2 + b_off + np*1280 + kk*32);
                LDSM4(bl[np], bb + 3*SMBLK*2 + b_off + np*1280 + kk*32);
            }
#pragma unroll
            for (int mt = 0; mt < 2; mt++)
#pragma unroll
                for (int nt = 0; nt < 8; nt++) {
                    int np = nt >> 1, sel = (nt & 1) * 2;
                    MMA16816(c[mt][nt], ah[mt], &bh[np][sel]);
                    MMA16816(c[mt][nt], ah[mt], &bl[np][sel]);
                    MMA16816(c[mt][nt], al[mt], &bh[np][sel]);
                }
        }
        __syncthreads();
    }

#pragma unroll
    for (int mt = 0; mt < 2; mt++) {
        int m = m0 + bm + mt * 16 + (lane >> 2);
#pragma unroll
        for (int nt = 0; nt < 8; nt++) {
            int n = n0 + bn + nt * 8 + (lane & 3) * 2;
            int dir = n >= G3;
            int g = n - dir * G3;
            float b0v = bih[n], b1v = bih[n + 1];
            float* o = g_XG[dir];
            o[(size_t)m * G3 + g]           = c[mt][nt][0] + b0v;
            o[(size_t)m * G3 + g + 1]       = c[mt][nt][1] + b1v;
            o[(size_t)(m + 8) * G3 + g]     = c[mt][nt][2] + b0v;
            o[(size_t)(m + 8) * G3 + g + 1] = c[mt][nt][3] + b1v;
        }
    }
}

// ---------------- fast gate math ----------------
__device__ __forceinline__ float fsigmoid(float x) {
    return __fdividef(1.f, 1.f + __expf(-x));
}
__device__ __forceinline__ float ftanh_(float x) {
    return 1.f - __fdividef(2.f, __expf(2.f * x) + 1.f);
}

// ---------------- persistent bidirectional GRU layer ----------------
// Decentralized sync: per-CTA flag (release store, no atomics); consumer warp w
// waits only on its 8 producer CTAs (8w..8w+7). Double-buffered red scratch ->
// one __syncthreads per step; gate warps publish via named barrier + release.
__global__ void __launch_bounds__(RT, 1) gru_layer_k(
    const float* __restrict__ Whh,   // [2][1152][384]
    const float* __restrict__ bhh,   // [2][1152]
    float* __restrict__ dout, int layer)
{
    extern __shared__ char smc[];
    __nv_bfloat16* Bs = (__nv_bfloat16*)smc;             // [2][12][32][40] = 61440 B
    __nv_bfloat16* As = (__nv_bfloat16*)(smc + 61440);   // [2][12][16][40] = 30720 B
    float*        red = (float*)(smc + 92160);           // [2][6][3][16][9]= 20736 B

    int tid = threadIdx.x, lane = tid & 31, w = tid >> 5;
    int d   = blockIdx.x / RNC;
    int cid = blockIdx.x - d * RNC;
    int jb  = cid * RJ;
    int* flags = g_flags[layer][d];

    // ---- prologue: zero Bs, convert Whh slice to bf16 hi/lo ldmatrix layout ----
    for (int i = tid; i < 3840; i += RT) ((uint4*)Bs)[i] = make_uint4(0,0,0,0);
    __syncthreads();
    const float* W = Whh + (size_t)d * G3 * H_;
    for (int i = tid; i < 24 * H_; i += RT) {
        int n = i / H_;            // 0..23 : gate g = n>>3, jl = n&7
        int k = i - n * H_;
        int g = n >> 3, jl = n & 7;
        float v = W[(size_t)(g * H_ + jb + jl) * H_ + k];
        __nv_bfloat16 hi = __float2bfloat16_rn(v);
        __nv_bfloat16 lo = __float2bfloat16_rn(v - __bfloat162float(hi));
        int addr = (k >> 5) * 1280 + n * 40 + (k & 31);
        Bs[addr]         = hi;
        Bs[15360 + addr] = lo;
    }
    // zero OWN slice of h phase 0 (8 j-cols x 16 b x 2 planes = 1KB)
    if (tid < 32) {
        int p = tid >> 4, b0 = tid & 15;
        int idx = (jb >> 5) * 640 + b0 * 40 + (jb & 31);
        *(uint4*)&g_hbf[d][0][p][idx] = make_uint4(0,0,0,0);
    }

    // gate-thread constants (tid<128: one (jl,b) output)
    int jl = tid >> 4, b = tid & 15;
    int j_g = jb + jl;
    float bhr = 0.f, bhz = 0.f, bhn = 0.f, hp = 0.f;
    float xr = 0.f, xz = 0.f, xn = 0.f;
    const float* xgbase = g_XG[d];
    if (tid < 128) {
        const float* bb = bhh + d * G3;
        bhr = bb[j_g]; bhz = bb[H_ + j_g]; bhn = bb[2 * H_ + j_g];
        int pos0 = d ? (S - 1) : 0;
        const float* xrow = xgbase + (size_t)(pos0 * B_ + b) * G3;
        xr = xrow[j_g]; xz = xrow[H_ + j_g]; xn = xrow[2 * H_ + j_g];
    }
    __syncthreads();
    if (tid == 0)
        asm volatile("st.release.gpu.global.s32 [%0], %1;" :: "l"(flags + cid), "r"(1) : "memory");

    unsigned sbase = (unsigned)__cvta_generic_to_shared(smc);
    unsigned Ab = sbase + 61440;
    unsigned Bb = sbase;
    unsigned a_off = (unsigned)((lane & 15) * 80 + ((lane >> 4) & 1) * 16);
    unsigned b_off = (unsigned)((((lane >> 4) & 1) * 8 + (lane & 7)) * 80 + ((lane >> 3) & 1) * 16);
    const int* myflag = flags + 8 * w + (lane & 7);

    for (int t = 0; t < S; t++) {
        int pos = d ? (S - 1 - t) : t;

        // per-warp wait: this warp's 8 producer CTAs must have published step t
        {
            int v;
            do {
                asm volatile("ld.acquire.gpu.global.s32 %0, [%1];" : "=r"(v) : "l"(myflag) : "memory");
            } while (__any_sync(0xffffffffu, v < t + 1));
        }
        // warp-owned h staging: chunks 2w,2w+1, both planes (L2-sourced loads)
        {
            const uint4* src = (const uint4*)g_hbf[d][t & 1];
            uint4* dst = (uint4*)As;
#pragma unroll
            for (int q = 0; q < 10; q++) {
                int e  = q * 32 + lane;
                int p  = (e >= 160);
                int e2 = e - p * 160;
                int cc = (e2 >= 80);
                int off = e2 - cc * 80;
                int ui = p * 960 + (2 * w + cc) * 80 + off;
                dst[ui] = __ldcg(src + ui);
            }
        }
        __syncwarp();

        // tensor-core matvec: warp w handles k-chunks 2w, 2w+1
        float acc[3][4];
#pragma unroll
        for (int nt = 0; nt < 3; nt++)
#pragma unroll
            for (int q = 0; q < 4; q++) acc[nt][q] = 0.f;

#pragma unroll
        for (int cc = 0; cc < 2; cc++) {
            int ck = 2 * w + cc;
#pragma unroll
            for (int kk = 0; kk < 2; kk++) {
                unsigned ah[4], al[4], bh0[4], bh1[4], bl0[4], bl1[4];
                unsigned ab = Ab + ck * 1280 + a_off + kk * 32;
                LDSM4(ah, ab);
                LDSM4(al, ab + 15360);
                unsigned bb2 = Bb + ck * 2560 + b_off + kk * 32;
                LDSM4(bh0, bb2);
                LDSM4(bh1, bb2 + 1280);
                LDSM4(bl0, bb2 + 30720);
                LDSM4(bl1, bb2 + 30720 + 1280);
                MMA16816(acc[0], ah, &bh0[0]); MMA16816(acc[0], ah, &bl0[0]); MMA16816(acc[0], al, &bh0[0]);
                MMA16816(acc[1], ah, &bh0[2]); MMA16816(acc[1], ah, &bl0[2]); MMA16816(acc[1], al, &bh0[2]);
                MMA16816(acc[2], ah, &bh1[0]); MMA16816(acc[2], ah, &bl1[0]); MMA16816(acc[2], al, &bh1[0]);
            }
        }
        // dump partials into red[t&1]
        {
            float* rbuf = red + (t & 1) * 2592;
            int row = lane >> 2, colb = (lane & 3) * 2;
#pragma unroll
            for (int nt = 0; nt < 3; nt++) {
                float* rb = rbuf + ((w * 3 + nt) * 16 + row) * 9 + colb;
                rb[0]  = acc[nt][0];
                rb[1]  = acc[nt][1];
                rb[72] = acc[nt][2];
                rb[73] = acc[nt][3];
            }
        }
        __syncthreads();   // the ONE full-CTA sync per step

        // gate math + state update + publish (warps 0-3)
        if (tid < 128) {
            const float* rbuf = red + (t & 1) * 2592;
            float sr = bhr, sz = bhz, sn = bhn;
#pragma unroll
            for (int ww = 0; ww < 6; ww++) {
                sr += rbuf[((ww * 3 + 0) * 16 + b) * 9 + jl];
                sz += rbuf[((ww * 3 + 1) * 16 + b) * 9 + jl];
                sn += rbuf[((ww * 3 + 2) * 16 + b) * 9 + jl];
            }
            float rg = fsigmoid(xr + sr);
            float zg = fsigmoid(xz + sz);
            float ng = ftanh_(xn + rg * sn);
            float hv = (1.f - zg) * ng + zg * hp;
            hp = hv;
            __nv_bfloat16 hi = __float2bfloat16_rn(hv);
            __nv_bfloat16 lo = __float2bfloat16_rn(hv - __bfloat162float(hi));
            int haddr = (j_g >> 5) * 640 + b * 40 + (j_g & 31);
            g_hbf[d][(t + 1) & 1][0][haddr] = hi;
            g_hbf[d][(t + 1) & 1][1][haddr] = lo;
            if (layer == 2)
                dout[((size_t)(b * S + pos)) * D_ + d * H_ + j_g] = hv;
            else
                g_X[((size_t)(pos * B_ + b)) * D_ + d * H_ + j_g] = hv;
            // prefetch xg for t+1
            int tn = t + 1;
            if (tn < S) {
                int posn = d ? (S - 1 - tn) : tn;
                const float* xrow = xgbase + (size_t)(posn * B_ + b) * G3;
                xr = xrow[j_g]; xz = xrow[H_ + j_g]; xn = xrow[2 * H_ + j_g];
            }
            // join gate warps, then publish this CTA's step t+1 readiness
            asm volatile("bar.sync 1, 128;" ::: "memory");
            if (tid == 0 && t < S - 1)
                asm volatile("st.release.gpu.global.s32 [%0], %1;" :: "l"(flags + cid), "r"(t + 2) : "memory");
        }
    }
}

// ---------------- launch ----------------
extern "C" void kernel_launch(void* const* d_in, const int* in_sizes, int n_in,
                              void* d_out, int out_size) {
    const float* x    = (const float*)d_in[0];
    const float* W_ih = (const float*)d_in[1];
    const float* W_hh = (const float*)d_in[2];
    const float* b_ih = (const float*)d_in[3];
    const float* b_hh = (const float*)d_in[4];
    float* out = (float*)d_out;

    int gsm = 61440 + 30720 + 20736;                  // 112,896 B
    cudaFuncSetAttribute(gru_layer_k, cudaFuncAttributeMaxDynamicSharedMemorySize, gsm);
    int msm = 2 * 4 * SMBLK * 2;                      // 81,920 B
    cudaFuncSetAttribute(gemm_xg_k, cudaFuncAttributeMaxDynamicSharedMemorySize, msm);

    patchify_k<<<49152, 256>>>(x);
    for (int l = 0; l < 3; l++) {
        dim3 gg(2304 / 128, 16384 / 128);   // (18,128)
        gemm_xg_k<<<gg, 256, msm>>>(W_ih + (size_t)l * 2 * G3 * D_,
                                    b_ih + (size_t)l * 2 * G3);
        gru_layer_k<<<2 * RNC, RT, gsm>>>(W_hh + (size_t)l * 2 * G3 * H_,
                                          b_hh + (size_t)l * 2 * G3,
                                          out, l);
    }
}

// round 12
// speedup vs baseline: 1.2610x; 1.2610x over previous
#include <cuda_runtime.h>
#include <cuda_bf16.h>
#include <math.h>

#define S   1024
#define B_  16
#define D_  768
#define H_  384
#define G3  1152   // 3*H
#define RNC 48     // CTAs per direction in recurrence
#define RJ  8      // h-columns per CTA (384/48)
#define RT  192    // threads per recurrence CTA

// ---------------- scratch (device globals; no allocation) ----------------
__device__ float         g_X [S*B_*D_];        // layer input,  (s*16+b, 768)
__device__ float         g_XG[2][S*B_*G3];     // gate proj, [dir][(s*16+b)*1152+g]
__device__ __nv_bfloat16 g_hbf[2][2][2][7680]; // [dir][phase][hi/lo][12 chunk][16 b][40]
__device__ unsigned      g_ctr[3][2][192];     // [layer][dir][6 groups x 32-word pad]

// ---------------- patchify + counter reset ----------------
__global__ void patchify_k(const float* __restrict__ x) {
    unsigned gi = blockIdx.x * blockDim.x + threadIdx.x;
    if (gi < 3 * 2 * 192) ((unsigned*)g_ctr)[gi] = 0;
    unsigned j  = gi & 511;
    unsigned i  = (gi >> 9) & 511;
    unsigned bc = gi >> 18;
    unsigned c  = bc % 3;
    unsigned b  = bc / 3;
    unsigned s  = (i >> 4) * 32 + (j >> 4);
    unsigned k  = (((i & 15) << 4) + (j & 15)) * 3 + c;
    g_X[(size_t)(s * 16 + b) * 768 + k] = x[gi];
}

// ================= shared bf16 split helpers =================
#define SMBLK 5120          // halfs per GEMM buffer block (128 rows * 40)
#define ROWH  40            // padded row length in halfs (80 bytes)

__device__ __forceinline__ void split8(const float* v, uint4& H, uint4& L) {
    unsigned h[4], l[4];
#pragma unroll
    for (int i = 0; i < 4; i++) {
        float a = v[2*i], b = v[2*i+1];
        __nv_bfloat16 ha = __float2bfloat16_rn(a), hb = __float2bfloat16_rn(b);
        float ra = a - __bfloat162float(ha), rb = b - __bfloat162float(hb);
        __nv_bfloat16 la = __float2bfloat16_rn(ra), lb = __float2bfloat16_rn(rb);
        h[i] = (unsigned)__bfloat16_as_ushort(ha) | ((unsigned)__bfloat16_as_ushort(hb) << 16);
        l[i] = (unsigned)__bfloat16_as_ushort(la) | ((unsigned)__bfloat16_as_ushort(lb) << 16);
    }
    H = make_uint4(h[0], h[1], h[2], h[3]);
    L = make_uint4(l[0], l[1], l[2], l[3]);
}

#define LDSM4(r, addr) \
    asm volatile("ldmatrix.sync.aligned.m8n8.x4.shared.b16 {%0,%1,%2,%3},[%4];" \
        : "=r"((r)[0]), "=r"((r)[1]), "=r"((r)[2]), "=r"((r)[3]) : "r"(addr))

#define MMA16816(d, a, b) \
    asm volatile("mma.sync.aligned.m16n8k16.row.col.f32.bf16.bf16.f32 " \
        "{%0,%1,%2,%3},{%4,%5,%6,%7},{%8,%9},{%0,%1,%2,%3};" \
        : "+f"((d)[0]), "+f"((d)[1]), "+f"((d)[2]), "+f"((d)[3]) \
        : "r"((a)[0]), "r"((a)[1]), "r"((a)[2]), "r"((a)[3]), "r"((b)[0]), "r"((b)[1]))

// ================= bf16 split-3 tensor-core GEMM (R3-proven, verbatim) =================
__global__ void __launch_bounds__(256, 1) gemm_xg_k(const float* __restrict__ Wih,
                                                    const float* __restrict__ bih) {
    extern __shared__ __nv_bfloat16 SM[];   // [2 buf][4 blk: AH,AL,BH,BL][5120]
    int tid  = threadIdx.x;
    int lane = tid & 31;
    int w    = tid >> 5;
    int m0   = blockIdx.y * 128;
    int n0   = blockIdx.x * 128;
    int bm   = (w >> 1) * 32;
    int bn   = (w & 1) * 64;

    int r  = tid >> 1;
    int c0 = (tid & 1) * 16;
    const float* Ag = g_X + (size_t)(m0 + r) * 768 + c0;
    const float* Bg = Wih + (size_t)(n0 + r) * 768 + c0;

    unsigned sbase = (unsigned)__cvta_generic_to_shared(SM);
    unsigned a_off = (unsigned)((bm + (lane & 15)) * 80 + ((lane >> 4) & 1) * 16);
    unsigned b_off = (unsigned)((bn + ((lane >> 4) & 1) * 8 + (lane & 7)) * 80 + ((lane >> 3) & 1) * 16);

    float c[2][8][4];
#pragma unroll
    for (int i = 0; i < 2; i++)
#pragma unroll
        for (int j = 0; j < 8; j++)
#pragma unroll
            for (int q = 0; q < 4; q++) c[i][j][q] = 0.f;

    float av[16], bv[16];
#pragma unroll
    for (int i = 0; i < 4; i++) {
        *(float4*)(av + 4*i) = *(const float4*)(Ag + 4*i);
        *(float4*)(bv + 4*i) = *(const float4*)(Bg + 4*i);
    }

    for (int kc = 0; kc < 24; kc++) {
        int buf = kc & 1;
        __nv_bfloat16* base = SM + buf * 4 * SMBLK;
        {
            uint4 H0, L0, H1, L1;
            split8(av,     H0, L0);
            split8(av + 8, H1, L1);
            __syncthreads();
            *(uint4*)(base + 0*SMBLK + r*ROWH + c0)     = H0;
            *(uint4*)(base + 0*SMBLK + r*ROWH + c0 + 8) = H1;
            *(uint4*)(base + 1*SMBLK + r*ROWH + c0)     = L0;
            *(uint4*)(base + 1*SMBLK + r*ROWH + c0 + 8) = L1;
            split8(bv,     H0, L0);
            split8(bv + 8, H1, L1);
            *(uint4*)(base + 2*SMBLK + r*ROWH + c0)     = H0;
            *(uint4*)(base + 2*SMBLK + r*ROWH + c0 + 8) = H1;
            *(uint4*)(base + 3*SMBLK + r*ROWH + c0)     = L0;
            *(uint4*)(base + 3*SMBLK + r*ROWH + c0 + 8) = L1;
        }
        if (kc < 23) {
            const float* An = Ag + (kc + 1) * 32;
            const float* Bn = Bg + (kc + 1) * 32;
#pragma unroll
            for (int i = 0; i < 4; i++) {
                *(float4*)(av + 4*i) = *(const float4*)(An + 4*i);
                *(float4*)(bv + 4*i) = *(const float4*)(Bn + 4*i);
            }
        }
        __syncthreads();

        unsigned bb = sbase + (unsigned)(buf * 4 * SMBLK * 2);
#pragma unroll
        for (int kk = 0; kk < 2; kk++) {
            unsigned ah[2][4], al[2][4], bh[4][4], bl[4][4];
#pragma unroll
            for (int mt = 0; mt < 2; mt++) {
                LDSM4(ah[mt], bb + 0*SMBLK*2 + a_off + mt*1280 + kk*32);
                LDSM4(al[mt], bb + 1*SMBLK*2 + a_off + mt*1280 + kk*32);
            }
#pragma unroll
            for (int np = 0; np < 4; np++) {
                LDSM4(bh[np], bb + 2*SMBLK*2 + b_off + np*1280 + kk*32);
                LDSM4(bl[np], bb + 3*SMBLK*2 + b_off + np*1280 + kk*32);
            }
#pragma unroll
            for (int mt = 0; mt < 2; mt++)
#pragma unroll
                for (int nt = 0; nt < 8; nt++) {
                    int np = nt >> 1, sel = (nt & 1) * 2;
                    MMA16816(c[mt][nt], ah[mt], &bh[np][sel]);
                    MMA16816(c[mt][nt], ah[mt], &bl[np][sel]);
                    MMA16816(c[mt][nt], al[mt], &bh[np][sel]);
                }
        }
    }

    // epilogue: bias + scatter into g_XG[dir]
#pragma unroll
    for (int mt = 0; mt < 2; mt++) {
        int m = m0 + bm + mt * 16 + (lane >> 2);
#pragma unroll
        for (int nt = 0; nt < 8; nt++) {
            int n = n0 + bn + nt * 8 + (lane & 3) * 2;
            int dir = n >= G3;
            int g = n - dir * G3;
            float b0v = bih[n], b1v = bih[n + 1];
            float* o = g_XG[dir];
            o[(size_t)m * G3 + g]           = c[mt][nt][0] + b0v;
            o[(size_t)m * G3 + g + 1]       = c[mt][nt][1] + b1v;
            o[(size_t)(m + 8) * G3 + g]     = c[mt][nt][2] + b0v;
            o[(size_t)(m + 8) * G3 + g + 1] = c[mt][nt][3] + b1v;
        }
    }
}

// ---------------- grouped inter-CTA barrier: 6 counters, 128B apart ----------------
// Each CTA adds 1 to counter[cid/8]; release passes when all 6 reach 8*phase.
// Cuts single-address L2 atomic serialization (~48 x 27cyc) ~6x.
__device__ __forceinline__ void ctabar6(unsigned* base, int grp, unsigned tgt) {
    __syncthreads();
    if (threadIdx.x == 0) {
        asm volatile("red.release.gpu.global.add.u32 [%0], 1;" :: "l"(base + grp * 32) : "memory");
        unsigned v0, v1, v2, v3, v4, v5;
        do {
            asm volatile("ld.acquire.gpu.global.u32 %0, [%1];" : "=r"(v0) : "l"(base +   0) : "memory");
            asm volatile("ld.acquire.gpu.global.u32 %0, [%1];" : "=r"(v1) : "l"(base +  32) : "memory");
            asm volatile("ld.acquire.gpu.global.u32 %0, [%1];" : "=r"(v2) : "l"(base +  64) : "memory");
            asm volatile("ld.acquire.gpu.global.u32 %0, [%1];" : "=r"(v3) : "l"(base +  96) : "memory");
            asm volatile("ld.acquire.gpu.global.u32 %0, [%1];" : "=r"(v4) : "l"(base + 128) : "memory");
            asm volatile("ld.acquire.gpu.global.u32 %0, [%1];" : "=r"(v5) : "l"(base + 160) : "memory");
        } while (v0 < tgt || v1 < tgt || v2 < tgt || v3 < tgt || v4 < tgt || v5 < tgt);
    }
    __syncthreads();
}

// ---------------- persistent bidirectional GRU layer (R4-exact core) ----------------
__global__ void __launch_bounds__(RT, 1) gru_layer_k(
    const float* __restrict__ Whh,   // [2][1152][384]
    const float* __restrict__ bhh,   // [2][1152]
    float* __restrict__ dout, int layer)
{
    extern __shared__ char smc[];
    __nv_bfloat16* Bs = (__nv_bfloat16*)smc;             // [2][12][32][40] = 61440 B
    __nv_bfloat16* As = (__nv_bfloat16*)(smc + 61440);   // [2][12][16][40] = 30720 B
    float*        red = (float*)(smc + 92160);           // [6][3][16][9]   = 10368 B

    int tid = threadIdx.x, lane = tid & 31, w = tid >> 5;
    int d   = blockIdx.x / RNC;
    int cid = blockIdx.x - d * RNC;
    int jb  = cid * RJ;
    int grp = cid >> 3;                 // 0..5
    unsigned* cb = g_ctr[layer][d];

    // prologue: zero Bs, convert Whh slice to bf16 hi/lo ldmatrix layout
    for (int i = tid; i < 3840; i += RT) ((uint4*)Bs)[i] = make_uint4(0,0,0,0);
    __syncthreads();
    const float* W = Whh + (size_t)d * G3 * H_;
    for (int i = tid; i < 24 * H_; i += RT) {
        int n = i / H_;
        int k = i - n * H_;
        int g = n >> 3, jl = n & 7;
        float v = W[(size_t)(g * H_ + jb + jl) * H_ + k];
        __nv_bfloat16 hi = __float2bfloat16_rn(v);
        __nv_bfloat16 lo = __float2bfloat16_rn(v - __bfloat162float(hi));
        int addr = (k >> 5) * 1280 + n * 40 + (k & 31);
        Bs[addr]         = hi;
        Bs[15360 + addr] = lo;
    }
    // zero phase-0 h planes (all CTAs write zeros; benign race)
    {
        uint4* z = (uint4*)g_hbf[d][0];
        for (int i = tid; i < 1920; i += RT) z[i] = make_uint4(0,0,0,0);
    }

    int jl = tid >> 4, b = tid & 15;
    int j_g = jb + jl;
    float bhr = 0.f, bhz = 0.f, bhn = 0.f, hp = 0.f;
    if (tid < 128) {
        const float* bb = bhh + d * G3;
        bhr = bb[j_g]; bhz = bb[H_ + j_g]; bhn = bb[2 * H_ + j_g];
    }
    ctabar6(cb, grp, 8u);

    unsigned sbase = (unsigned)__cvta_generic_to_shared(smc);
    unsigned Ab = sbase + 61440;
    unsigned Bb = sbase;
    unsigned a_off = (unsigned)((lane & 15) * 80 + ((lane >> 4) & 1) * 16);
    unsigned b_off = (unsigned)((((lane >> 4) & 1) * 8 + (lane & 7)) * 80 + ((lane >> 3) & 1) * 16);
    const float* xgbase = g_XG[d];

    for (int t = 0; t < S; t++) {
        int pos = d ? (S - 1 - t) : t;

        // copy h planes (30KB) global -> SMEM A layout
        {
            const uint4* src = (const uint4*)g_hbf[d][t & 1];
            uint4* dst = (uint4*)As;
#pragma unroll
            for (int i = 0; i < 10; i++) dst[tid + i * RT] = src[tid + i * RT];
        }
        float xr = 0.f, xz = 0.f, xn = 0.f;
        if (tid < 128) {
            const float* xrow = xgbase + (size_t)(pos * B_ + b) * G3;
            xr = xrow[j_g]; xz = xrow[H_ + j_g]; xn = xrow[2 * H_ + j_g];
        }
        __syncthreads();

        float acc[3][4];
#pragma unroll
        for (int nt = 0; nt < 3; nt++)
#pragma unroll
            for (int q = 0; q < 4; q++) acc[nt][q] = 0.f;

#pragma unroll
        for (int cc = 0; cc < 2; cc++) {
            int ck = 2 * w + cc;
#pragma unroll
            for (int kk = 0; kk < 2; kk++) {
                unsigned ah[4], al[4], bh0[4], bh1[4], bl0[4], bl1[4];
                unsigned ab = Ab + ck * 1280 + a_off + kk * 32;
                LDSM4(ah, ab);
                LDSM4(al, ab + 15360);
                unsigned bb2 = Bb + ck * 2560 + b_off + kk * 32;
                LDSM4(bh0, bb2);
                LDSM4(bh1, bb2 + 1280);
                LDSM4(bl0, bb2 + 30720);
                LDSM4(bl1, bb2 + 30720 + 1280);
                MMA16816(acc[0], ah, &bh0[0]); MMA16816(acc[0], ah, &bl0[0]); MMA16816(acc[0], al, &bh0[0]);
                MMA16816(acc[1], ah, &bh0[2]); MMA16816(acc[1], ah, &bl0[2]); MMA16816(acc[1], al, &bh0[2]);
                MMA16816(acc[2], ah, &bh1[0]); MMA16816(acc[2], ah, &bl1[0]); MMA16816(acc[2], al, &bh1[0]);
            }
        }
        {
            int row = lane >> 2, colb = (lane & 3) * 2;
#pragma unroll
            for (int nt = 0; nt < 3; nt++) {
                float* rb = red + ((w * 3 + nt) * 16 + row) * 9 + colb;
                rb[0]  = acc[nt][0];
                rb[1]  = acc[nt][1];
                rb[72] = acc[nt][2];
                rb[73] = acc[nt][3];
            }
        }
        __syncthreads();

        if (tid < 128) {
            float sr = bhr, sz = bhz, sn = bhn;
#pragma unroll
            for (int ww = 0; ww < 6; ww++) {
                sr += red[((ww * 3 + 0) * 16 + b) * 9 + jl];
                sz += red[((ww * 3 + 1) * 16 + b) * 9 + jl];
                sn += red[((ww * 3 + 2) * 16 + b) * 9 + jl];
            }
            float rg = 1.f / (1.f + expf(-(xr + sr)));
            float zg = 1.f / (1.f + expf(-(xz + sz)));
            float ng = tanhf(xn + rg * sn);
            float hv = (1.f - zg) * ng + zg * hp;
            hp = hv;
            __nv_bfloat16 hi = __float2bfloat16_rn(hv);
            __nv_bfloat16 lo = __float2bfloat16_rn(hv - __bfloat162float(hi));
            int haddr = (j_g >> 5) * 640 + b * 40 + (j_g & 31);
            g_hbf[d][(t + 1) & 1][0][haddr] = hi;
            g_hbf[d][(t + 1) & 1][1][haddr] = lo;
            if (layer == 2)
                dout[((size_t)(b * S + pos)) * D_ + d * H_ + j_g] = hv;
            else
                g_X[((size_t)(pos * B_ + b)) * D_ + d * H_ + j_g] = hv;
        }

        if (t < S - 1) ctabar6(cb, grp, 8u * (t + 2));
    }
}

// ---------------- launch ----------------
extern "C" void kernel_launch(void* const* d_in, const int* in_sizes, int n_in,
                              void* d_out, int out_size) {
    const float* x    = (const float*)d_in[0];
    const float* W_ih = (const float*)d_in[1];
    const float* W_hh = (const float*)d_in[2];
    const float* b_ih = (const float*)d_in[3];
    const float* b_hh = (const float*)d_in[4];
    float* out = (float*)d_out;

    int gsm = 61440 + 30720 + 10368;                  // 102,528 B
    cudaFuncSetAttribute(gru_layer_k, cudaFuncAttributeMaxDynamicSharedMemorySize, gsm);
    int msm = 2 * 4 * SMBLK * 2;                      // 81,920 B
    cudaFuncSetAttribute(gemm_xg_k, cudaFuncAttributeMaxDynamicSharedMemorySize, msm);

    patchify_k<<<49152, 256>>>(x);
    for (int l = 0; l < 3; l++) {
        dim3 gg(2304 / 128, 16384 / 128);   // (18,128)
        gemm_xg_k<<<gg, 256, msm>>>(W_ih + (size_t)l * 2 * G3 * D_,
                                    b_ih + (size_t)l * 2 * G3);
        gru_layer_k<<<2 * RNC, RT, gsm>>>(W_hh + (size_t)l * 2 * G3 * H_,
                                          b_hh + (size_t)l * 2 * G3,
                                          out, l);
    }
}

// round 13
// speedup vs baseline: 1.7293x; 1.3714x over previous
#include <cuda_runtime.h>
#include <cuda_bf16.h>
#include <math.h>

#define S   1024
#define B_  16
#define D_  768
#define H_  384
#define G3  1152   // 3*H
#define RNC 48     // CTAs per direction in recurrence
#define RJ  8      // h-columns per CTA (384/48)
#define RT  192    // threads per recurrence CTA

// ---------------- scratch (device globals; no allocation) ----------------
__device__ float         g_X [S*B_*D_];        // layer input,  (s*16+b, 768)
__device__ float         g_XG[2][S*B_*G3];     // gate proj, [dir][(s*16+b)*1152+g]
__device__ __nv_bfloat16 g_hbf[2][2][2][7680]; // [dir][phase][hi/lo][12 chunk][16 b][40]
__device__ unsigned      g_ctr[3][2];          // [layer][dir] barrier counters

// ---------------- patchify + counter reset (R4-exact) ----------------
__global__ void patchify_k(const float* __restrict__ x) {
    unsigned gi = blockIdx.x * blockDim.x + threadIdx.x;
    if (gi < 6) ((unsigned*)g_ctr)[gi] = 0;
    unsigned j  = gi & 511;
    unsigned i  = (gi >> 9) & 511;
    unsigned bc = gi >> 18;
    unsigned c  = bc % 3;
    unsigned b  = bc / 3;
    unsigned s  = (i >> 4) * 32 + (j >> 4);
    unsigned k  = (((i & 15) << 4) + (j & 15)) * 3 + c;
    g_X[(size_t)(s * 16 + b) * 768 + k] = x[gi];
}

// ================= shared bf16 split helpers =================
__device__ __forceinline__ void split8(const float* v, uint4& H, uint4& L) {
    unsigned h[4], l[4];
#pragma unroll
    for (int i = 0; i < 4; i++) {
        float a = v[2*i], b = v[2*i+1];
        __nv_bfloat16 ha = __float2bfloat16_rn(a), hb = __float2bfloat16_rn(b);
        float ra = a - __bfloat162float(ha), rb = b - __bfloat162float(hb);
        __nv_bfloat16 la = __float2bfloat16_rn(ra), lb = __float2bfloat16_rn(rb);
        h[i] = (unsigned)__bfloat16_as_ushort(ha) | ((unsigned)__bfloat16_as_ushort(hb) << 16);
        l[i] = (unsigned)__bfloat16_as_ushort(la) | ((unsigned)__bfloat16_as_ushort(lb) << 16);
    }
    H = make_uint4(h[0], h[1], h[2], h[3]);
    L = make_uint4(l[0], l[1], l[2], l[3]);
}

#define LDSM4(r, addr) \
    asm volatile("ldmatrix.sync.aligned.m8n8.x4.shared.b16 {%0,%1,%2,%3},[%4];" \
        : "=r"((r)[0]), "=r"((r)[1]), "=r"((r)[2]), "=r"((r)[3]) : "r"(addr))

#define MMA16816(d, a, b) \
    asm volatile("mma.sync.aligned.m16n8k16.row.col.f32.bf16.bf16.f32 " \
        "{%0,%1,%2,%3},{%4,%5,%6,%7},{%8,%9},{%0,%1,%2,%3};" \
        : "+f"((d)[0]), "+f"((d)[1]), "+f"((d)[2]), "+f"((d)[3]) \
        : "r"((a)[0]), "r"((a)[1]), "r"((a)[2]), "r"((a)[3]), "r"((b)[0]), "r"((b)[1]))

// ================= bf16 split-3 tensor-core GEMM: 64x128 tile, 3 CTAs/SM =========
// XG = X * Wih^T + bih.  M=16384, N=2304 (both dirs), K=768.
// CTA 64x128, BK=32, 128 threads (4 warps of 32x64 — identical per-warp compute
// to the proven 182-reg kernel).  Direct LDG->split->STS staging (no B prefetch
// registers); stalls hidden by 3 co-resident CTAs.
#define ABLK 2560            // halfs per A block (64 rows * 40)
#define BBLK 5120            // halfs per B block (128 rows * 40)
#define BUFH (2*ABLK + 2*BBLK)   // 15360 halfs / buffer (30,720 B)

__global__ void __launch_bounds__(128, 3) gemm_xg_k(const float* __restrict__ Wih,
                                                    const float* __restrict__ bih) {
    extern __shared__ __nv_bfloat16 SM[];   // [2 buf][AH 64x40 | AL 64x40 | BH 128x40 | BL 128x40]
    int tid  = threadIdx.x;
    int lane = tid & 31;
    int w    = tid >> 5;            // 0..3
    int m0   = blockIdx.y * 64;
    int n0   = blockIdx.x * 128;
    int bm   = (w >> 1) * 32;       // warp m base (0,32)
    int bn   = (w & 1) * 64;        // warp n base (0,64)

    // staging coords
    int rA = tid >> 1;              // 0..63
    int cA = (tid & 1) * 16;        // half-row select (16 halfs)
    int rB = tid;                   // 0..127 (full row, 4 groups of 8)
    const float* Ag = g_X + (size_t)(m0 + rA) * 768 + cA;
    const float* Bg = Wih + (size_t)(n0 + rB) * 768;

    unsigned sbase = (unsigned)__cvta_generic_to_shared(SM);
    unsigned a_off = (unsigned)((bm + (lane & 15)) * 80 + ((lane >> 4) & 1) * 16);
    unsigned b_off = (unsigned)((bn + ((lane >> 4) & 1) * 8 + (lane & 7)) * 80 + ((lane >> 3) & 1) * 16);

    float c[2][8][4];
#pragma unroll
    for (int i = 0; i < 2; i++)
#pragma unroll
        for (int j = 0; j < 8; j++)
#pragma unroll
            for (int q = 0; q < 4; q++) c[i][j][q] = 0.f;

    for (int kc = 0; kc < 24; kc++) {
        __nv_bfloat16* base = SM + (kc & 1) * BUFH;
        __syncthreads();   // buffer (kc&1) free: its readers (compute kc-2) passed sync of kc-1
        // A: 16 floats -> hi/lo
        {
            float av[16];
#pragma unroll
            for (int i = 0; i < 4; i++)
                *(float4*)(av + 4*i) = *(const float4*)(Ag + kc * 32 + 4*i);
            uint4 H0, L0, H1, L1;
            split8(av,     H0, L0);
            split8(av + 8, H1, L1);
            *(uint4*)(base + rA*40 + cA)            = H0;
            *(uint4*)(base + rA*40 + cA + 8)        = H1;
            *(uint4*)(base + ABLK + rA*40 + cA)     = L0;
            *(uint4*)(base + ABLK + rA*40 + cA + 8) = L1;
        }
        // B: full 32-float row in 4 groups of 8
#pragma unroll
        for (int hh = 0; hh < 4; hh++) {
            float bv[8];
            *(float4*)(bv)     = *(const float4*)(Bg + kc * 32 + hh * 8);
            *(float4*)(bv + 4) = *(const float4*)(Bg + kc * 32 + hh * 8 + 4);
            uint4 Hx, Lx;
            split8(bv, Hx, Lx);
            *(uint4*)(base + 2*ABLK + rB*40 + hh*8)        = Hx;
            *(uint4*)(base + 2*ABLK + BBLK + rB*40 + hh*8) = Lx;
        }
        __syncthreads();

        unsigned bb = sbase + (unsigned)((kc & 1) * BUFH * 2);
#pragma unroll
        for (int kk = 0; kk < 2; kk++) {
            unsigned ah[2][4], al[2][4], bh[4][4], bl[4][4];
#pragma unroll
            for (int mt = 0; mt < 2; mt++) {
                LDSM4(ah[mt], bb + a_off + mt*1280 + kk*32);
                LDSM4(al[mt], bb + ABLK*2 + a_off + mt*1280 + kk*32);
            }
#pragma unroll
            for (int np = 0; np < 4; np++) {
                LDSM4(bh[np], bb + 2*ABLK*2 + b_off + np*1280 + kk*32);
                LDSM4(bl[np], bb + (2*ABLK + BBLK)*2 + b_off + np*1280 + kk*32);
            }
#pragma unroll
            for (int mt = 0; mt < 2; mt++)
#pragma unroll
                for (int nt = 0; nt < 8; nt++) {
                    int np = nt >> 1, sel = (nt & 1) * 2;
                    MMA16816(c[mt][nt], ah[mt], &bh[np][sel]);
                    MMA16816(c[mt][nt], ah[mt], &bl[np][sel]);
                    MMA16816(c[mt][nt], al[mt], &bh[np][sel]);
                }
        }
    }

    // epilogue: bias + scatter into g_XG[dir]
#pragma unroll
    for (int mt = 0; mt < 2; mt++) {
        int m = m0 + bm + mt * 16 + (lane >> 2);
#pragma unroll
        for (int nt = 0; nt < 8; nt++) {
            int n = n0 + bn + nt * 8 + (lane & 3) * 2;
            int dir = n >= G3;
            int g = n - dir * G3;
            float b0v = bih[n], b1v = bih[n + 1];
            float* o = g_XG[dir];
            o[(size_t)m * G3 + g]           = c[mt][nt][0] + b0v;
            o[(size_t)m * G3 + g + 1]       = c[mt][nt][1] + b1v;
            o[(size_t)(m + 8) * G3 + g]     = c[mt][nt][2] + b0v;
            o[(size_t)(m + 8) * G3 + g + 1] = c[mt][nt][3] + b1v;
        }
    }
}

// ---------------- inter-CTA barrier (single counter; R4-proven) ----------------
__device__ __forceinline__ void ctabar(unsigned* c, unsigned target) {
    __syncthreads();
    if (threadIdx.x == 0) {
        asm volatile("red.release.gpu.global.add.u32 [%0], 1;" :: "l"(c) : "memory");
        unsigned v;
        do {
            asm volatile("ld.acquire.gpu.global.u32 %0, [%1];" : "=r"(v) : "l"(c) : "memory");
        } while (v < target);
    }
    __syncthreads();
}

// ---------------- persistent bidirectional GRU layer (R4-exact) ----------------
__global__ void __launch_bounds__(RT, 1) gru_layer_k(
    const float* __restrict__ Whh,   // [2][1152][384]
    const float* __restrict__ bhh,   // [2][1152]
    float* __restrict__ dout, int layer)
{
    extern __shared__ char smc[];
    __nv_bfloat16* Bs = (__nv_bfloat16*)smc;             // [2][12][32][40] = 61440 B
    __nv_bfloat16* As = (__nv_bfloat16*)(smc + 61440);   // [2][12][16][40] = 30720 B
    float*        red = (float*)(smc + 92160);           // [6][3][16][9]   = 10368 B

    int tid = threadIdx.x, lane = tid & 31, w = tid >> 5;
    int d   = blockIdx.x / RNC;
    int cid = blockIdx.x - d * RNC;
    int jb  = cid * RJ;
    unsigned* ctr = &g_ctr[layer][d];

    // prologue: zero Bs, convert Whh slice to bf16 hi/lo ldmatrix layout
    for (int i = tid; i < 3840; i += RT) ((uint4*)Bs)[i] = make_uint4(0,0,0,0);
    __syncthreads();
    const float* W = Whh + (size_t)d * G3 * H_;
    for (int i = tid; i < 24 * H_; i += RT) {
        int n = i / H_;
        int k = i - n * H_;
        int g = n >> 3, jl = n & 7;
        float v = W[(size_t)(g * H_ + jb + jl) * H_ + k];
        __nv_bfloat16 hi = __float2bfloat16_rn(v);
        __nv_bfloat16 lo = __float2bfloat16_rn(v - __bfloat162float(hi));
        int addr = (k >> 5) * 1280 + n * 40 + (k & 31);
        Bs[addr]         = hi;
        Bs[15360 + addr] = lo;
    }
    // zero phase-0 h planes (all CTAs write zeros; benign race)
    {
        uint4* z = (uint4*)g_hbf[d][0];
        for (int i = tid; i < 1920; i += RT) z[i] = make_uint4(0,0,0,0);
    }

    int jl = tid >> 4, b = tid & 15;
    int j_g = jb + jl;
    float bhr = 0.f, bhz = 0.f, bhn = 0.f, hp = 0.f;
    if (tid < 128) {
        const float* bb = bhh + d * G3;
        bhr = bb[j_g]; bhz = bb[H_ + j_g]; bhn = bb[2 * H_ + j_g];
    }
    ctabar(ctr, RNC);

    unsigned sbase = (unsigned)__cvta_generic_to_shared(smc);
    unsigned Ab = sbase + 61440;
    unsigned Bb = sbase;
    unsigned a_off = (unsigned)((lane & 15) * 80 + ((lane >> 4) & 1) * 16);
    unsigned b_off = (unsigned)((((lane >> 4) & 1) * 8 + (lane & 7)) * 80 + ((lane >> 3) & 1) * 16);
    const float* xgbase = g_XG[d];

    for (int t = 0; t < S; t++) {
        int pos = d ? (S - 1 - t) : t;

        // copy h planes (30KB) global -> SMEM A layout
        {
            const uint4* src = (const uint4*)g_hbf[d][t & 1];
            uint4* dst = (uint4*)As;
#pragma unroll
            for (int i = 0; i < 10; i++) dst[tid + i * RT] = src[tid + i * RT];
        }
        float xr = 0.f, xz = 0.f, xn = 0.f;
        if (tid < 128) {
            const float* xrow = xgbase + (size_t)(pos * B_ + b) * G3;
            xr = xrow[j_g]; xz = xrow[H_ + j_g]; xn = xrow[2 * H_ + j_g];
        }
        __syncthreads();

        float acc[3][4];
#pragma unroll
        for (int nt = 0; nt < 3; nt++)
#pragma unroll
            for (int q = 0; q < 4; q++) acc[nt][q] = 0.f;

#pragma unroll
        for (int cc = 0; cc < 2; cc++) {
            int ck = 2 * w + cc;
#pragma unroll
            for (int kk = 0; kk < 2; kk++) {
                unsigned ah[4], al[4], bh0[4], bh1[4], bl0[4], bl1[4];
                unsigned ab = Ab + ck * 1280 + a_off + kk * 32;
                LDSM4(ah, ab);
                LDSM4(al, ab + 15360);
                unsigned bb2 = Bb + ck * 2560 + b_off + kk * 32;
                LDSM4(bh0, bb2);
                LDSM4(bh1, bb2 + 1280);
                LDSM4(bl0, bb2 + 30720);
                LDSM4(bl1, bb2 + 30720 + 1280);
                MMA16816(acc[0], ah, &bh0[0]); MMA16816(acc[0], ah, &bl0[0]); MMA16816(acc[0], al, &bh0[0]);
                MMA16816(acc[1], ah, &bh0[2]); MMA16816(acc[1], ah, &bl0[2]); MMA16816(acc[1], al, &bh0[2]);
                MMA16816(acc[2], ah, &bh1[0]); MMA16816(acc[2], ah, &bl1[0]); MMA16816(acc[2], al, &bh1[0]);
            }
        }
        {
            int row = lane >> 2, colb = (lane & 3) * 2;
#pragma unroll
            for (int nt = 0; nt < 3; nt++) {
                float* rb = red + ((w * 3 + nt) * 16 + row) * 9 + colb;
                rb[0]  = acc[nt][0];
                rb[1]  = acc[nt][1];
                rb[72] = acc[nt][2];
                rb[73] = acc[nt][3];
            }
        }
        __syncthreads();

        if (tid < 128) {
            float sr = bhr, sz = bhz, sn = bhn;
#pragma unroll
            for (int ww = 0; ww < 6; ww++) {
                sr += red[((ww * 3 + 0) * 16 + b) * 9 + jl];
                sz += red[((ww * 3 + 1) * 16 + b) * 9 + jl];
                sn += red[((ww * 3 + 2) * 16 + b) * 9 + jl];
            }
            float rg = 1.f / (1.f + expf(-(xr + sr)));
            float zg = 1.f / (1.f + expf(-(xz + sz)));
            float ng = tanhf(xn + rg * sn);
            float hv = (1.f - zg) * ng + zg * hp;
            hp = hv;
            __nv_bfloat16 hi = __float2bfloat16_rn(hv);
            __nv_bfloat16 lo = __float2bfloat16_rn(hv - __bfloat162float(hi));
            int haddr = (j_g >> 5) * 640 + b * 40 + (j_g & 31);
            g_hbf[d][(t + 1) & 1][0][haddr] = hi;
            g_hbf[d][(t + 1) & 1][1][haddr] = lo;
            if (layer == 2)
                dout[((size_t)(b * S + pos)) * D_ + d * H_ + j_g] = hv;
            else
                g_X[((size_t)(pos * B_ + b)) * D_ + d * H_ + j_g] = hv;
        }

        if (t < S - 1) ctabar(ctr, (unsigned)RNC * (t + 2));
    }
}

// ---------------- launch ----------------
extern "C" void kernel_launch(void* const* d_in, const int* in_sizes, int n_in,
                              void* d_out, int out_size) {
    const float* x    = (const float*)d_in[0];
    const float* W_ih = (const float*)d_in[1];
    const float* W_hh = (const float*)d_in[2];
    const float* b_ih = (const float*)d_in[3];
    const float* b_hh = (const float*)d_in[4];
    float* out = (float*)d_out;

    int gsm = 61440 + 30720 + 10368;                  // 102,528 B
    cudaFuncSetAttribute(gru_layer_k, cudaFuncAttributeMaxDynamicSharedMemorySize, gsm);
    int msm = 2 * BUFH * 2;                           // 61,440 B
    cudaFuncSetAttribute(gemm_xg_k, cudaFuncAttributeMaxDynamicSharedMemorySize, msm);

    patchify_k<<<49152, 256>>>(x);
    for (int l = 0; l < 3; l++) {
        dim3 gg(2304 / 128, 16384 / 64);   // (18,256)
        gemm_xg_k<<<gg, 128, msm>>>(W_ih + (size_t)l * 2 * G3 * D_,
                                    b_ih + (size_t)l * 2 * G3);
        gru_layer_k<<<2 * RNC, RT, gsm>>>(W_hh + (size_t)l * 2 * G3 * H_,
                                          b_hh + (size_t)l * 2 * G3,
                                          out, l);
    }
}

// round 14
// speedup vs baseline: 1.8091x; 1.0461x over previous
#include <cuda_runtime.h>
#include <cuda_bf16.h>
#include <math.h>

#define S   1024
#define B_  16
#define D_  768
#define H_  384
#define G3  1152   // 3*H
#define RNC 24     // CTAs per sync group (dir x batch-half)
#define RJ  16     // h-columns per CTA (384/24)
#define RT  192    // threads per recurrence CTA

// ---------------- scratch (device globals; no allocation) ----------------
__device__ float         g_X [S*B_*D_];          // layer input,  (s*16+b, 768)
__device__ float         g_XG[2][S*B_*G3];       // gate proj, [dir][(s*16+b)*1152+g]
__device__ __nv_bfloat16 g_hA[2][2][2][2][3840]; // [d][bh][phase][hi/lo][12 chunk][8 b][40]
__device__ unsigned      g_ctr[3][2][2][32];     // [layer][d][bh] counters, 128B apart

// ---------------- patchify + counter reset ----------------
__global__ void patchify_k(const float* __restrict__ x) {
    unsigned gi = blockIdx.x * blockDim.x + threadIdx.x;
    if (gi < 3 * 2 * 2 * 32) ((unsigned*)g_ctr)[gi] = 0;
    unsigned j  = gi & 511;
    unsigned i  = (gi >> 9) & 511;
    unsigned bc = gi >> 18;
    unsigned c  = bc % 3;
    unsigned b  = bc / 3;
    unsigned s  = (i >> 4) * 32 + (j >> 4);
    unsigned k  = (((i & 15) << 4) + (j & 15)) * 3 + c;
    g_X[(size_t)(s * 16 + b) * 768 + k] = x[gi];
}

// ================= shared bf16 split helpers =================
#define SMBLK 5120          // halfs per GEMM buffer block (128 rows * 40)
#define ROWH  40            // padded row length in halfs (80 bytes)

__device__ __forceinline__ void split8(const float* v, uint4& H, uint4& L) {
    unsigned h[4], l[4];
#pragma unroll
    for (int i = 0; i < 4; i++) {
        float a = v[2*i], b = v[2*i+1];
        __nv_bfloat16 ha = __float2bfloat16_rn(a), hb = __float2bfloat16_rn(b);
        float ra = a - __bfloat162float(ha), rb = b - __bfloat162float(hb);
        __nv_bfloat16 la = __float2bfloat16_rn(ra), lb = __float2bfloat16_rn(rb);
        h[i] = (unsigned)__bfloat16_as_ushort(ha) | ((unsigned)__bfloat16_as_ushort(hb) << 16);
        l[i] = (unsigned)__bfloat16_as_ushort(la) | ((unsigned)__bfloat16_as_ushort(lb) << 16);
    }
    H = make_uint4(h[0], h[1], h[2], h[3]);
    L = make_uint4(l[0], l[1], l[2], l[3]);
}

#define LDSM4(r, addr) \
    asm volatile("ldmatrix.sync.aligned.m8n8.x4.shared.b16 {%0,%1,%2,%3},[%4];" \
        : "=r"((r)[0]), "=r"((r)[1]), "=r"((r)[2]), "=r"((r)[3]) : "r"(addr))

#define MMA16816(d, a, b) \
    asm volatile("mma.sync.aligned.m16n8k16.row.col.f32.bf16.bf16.f32 " \
        "{%0,%1,%2,%3},{%4,%5,%6,%7},{%8,%9},{%0,%1,%2,%3};" \
        : "+f"((d)[0]), "+f"((d)[1]), "+f"((d)[2]), "+f"((d)[3]) \
        : "r"((a)[0]), "r"((a)[1]), "r"((a)[2]), "r"((a)[3]), "r"((b)[0]), "r"((b)[1]))

// ================= bf16 split-3 tensor-core GEMM (R3/R4/R12-proven, verbatim) ======
__global__ void __launch_bounds__(256, 1) gemm_xg_k(const float* __restrict__ Wih,
                                                    const float* __restrict__ bih) {
    extern __shared__ __nv_bfloat16 SM[];   // [2 buf][4 blk: AH,AL,BH,BL][5120]
    int tid  = threadIdx.x;
    int lane = tid & 31;
    int w    = tid >> 5;
    int m0   = blockIdx.y * 128;
    int n0   = blockIdx.x * 128;
    int bm   = (w >> 1) * 32;
    int bn   = (w & 1) * 64;

    int r  = tid >> 1;
    int c0 = (tid & 1) * 16;
    const float* Ag = g_X + (size_t)(m0 + r) * 768 + c0;
    const float* Bg = Wih + (size_t)(n0 + r) * 768 + c0;

    unsigned sbase = (unsigned)__cvta_generic_to_shared(SM);
    unsigned a_off = (unsigned)((bm + (lane & 15)) * 80 + ((lane >> 4) & 1) * 16);
    unsigned b_off = (unsigned)((bn + ((lane >> 4) & 1) * 8 + (lane & 7)) * 80 + ((lane >> 3) & 1) * 16);

    float c[2][8][4];
#pragma unroll
    for (int i = 0; i < 2; i++)
#pragma unroll
        for (int j = 0; j < 8; j++)
#pragma unroll
            for (int q = 0; q < 4; q++) c[i][j][q] = 0.f;

    float av[16], bv[16];
#pragma unroll
    for (int i = 0; i < 4; i++) {
        *(float4*)(av + 4*i) = *(const float4*)(Ag + 4*i);
        *(float4*)(bv + 4*i) = *(const float4*)(Bg + 4*i);
    }

    for (int kc = 0; kc < 24; kc++) {
        int buf = kc & 1;
        __nv_bfloat16* base = SM + buf * 4 * SMBLK;
        {
            uint4 H0, L0, H1, L1;
            split8(av,     H0, L0);
            split8(av + 8, H1, L1);
            __syncthreads();
            *(uint4*)(base + 0*SMBLK + r*ROWH + c0)     = H0;
            *(uint4*)(base + 0*SMBLK + r*ROWH + c0 + 8) = H1;
            *(uint4*)(base + 1*SMBLK + r*ROWH + c0)     = L0;
            *(uint4*)(base + 1*SMBLK + r*ROWH + c0 + 8) = L1;
            split8(bv,     H0, L0);
            split8(bv + 8, H1, L1);
            *(uint4*)(base + 2*SMBLK + r*ROWH + c0)     = H0;
            *(uint4*)(base + 2*SMBLK + r*ROWH + c0 + 8) = H1;
            *(uint4*)(base + 3*SMBLK + r*ROWH + c0)     = L0;
            *(uint4*)(base + 3*SMBLK + r*ROWH + c0 + 8) = L1;
        }
        if (kc < 23) {
            const float* An = Ag + (kc + 1) * 32;
            const float* Bn = Bg + (kc + 1) * 32;
#pragma unroll
            for (int i = 0; i < 4; i++) {
                *(float4*)(av + 4*i) = *(const float4*)(An + 4*i);
                *(float4*)(bv + 4*i) = *(const float4*)(Bn + 4*i);
            }
        }
        __syncthreads();

        unsigned bb = sbase + (unsigned)(buf * 4 * SMBLK * 2);
#pragma unroll
        for (int kk = 0; kk < 2; kk++) {
            unsigned ah[2][4], al[2][4], bh[4][4], bl[4][4];
#pragma unroll
            for (int mt = 0; mt < 2; mt++) {
                LDSM4(ah[mt], bb + 0*SMBLK*2 + a_off + mt*1280 + kk*32);
                LDSM4(al[mt], bb + 1*SMBLK*2 + a_off + mt*1280 + kk*32);
            }
#pragma unroll
            for (int np = 0; np < 4; np++) {
                LDSM4(bh[np], bb + 2*SMBLK*2 + b_off + np*1280 + kk*32);
                LDSM4(bl[np], bb + 3*SMBLK*2 + b_off + np*1280 + kk*32);
            }
#pragma unroll
            for (int mt = 0; mt < 2; mt++)
#pragma unroll
                for (int nt = 0; nt < 8; nt++) {
                    int np = nt >> 1, sel = (nt & 1) * 2;
                    MMA16816(c[mt][nt], ah[mt], &bh[np][sel]);
                    MMA16816(c[mt][nt], ah[mt], &bl[np][sel]);
                    MMA16816(c[mt][nt], al[mt], &bh[np][sel]);
                }
        }
    }

#pragma unroll
    for (int mt = 0; mt < 2; mt++) {
        int m = m0 + bm + mt * 16 + (lane >> 2);
#pragma unroll
        for (int nt = 0; nt < 8; nt++) {
            int n = n0 + bn + nt * 8 + (lane & 3) * 2;
            int dir = n >= G3;
            int g = n - dir * G3;
            float b0v = bih[n], b1v = bih[n + 1];
            float* o = g_XG[dir];
            o[(size_t)m * G3 + g]           = c[mt][nt][0] + b0v;
            o[(size_t)m * G3 + g + 1]       = c[mt][nt][1] + b1v;
            o[(size_t)(m + 8) * G3 + g]     = c[mt][nt][2] + b0v;
            o[(size_t)(m + 8) * G3 + g + 1] = c[mt][nt][3] + b1v;
        }
    }
}

// ---------------- inter-CTA barrier (single counter per group; R4-proven) ----------
__device__ __forceinline__ void ctabar(unsigned* c, unsigned target) {
    __syncthreads();
    if (threadIdx.x == 0) {
        asm volatile("red.release.gpu.global.add.u32 [%0], 1;" :: "l"(c) : "memory");
        unsigned v;
        do {
            asm volatile("ld.acquire.gpu.global.u32 %0, [%1];" : "=r"(v) : "l"(c) : "memory");
        } while (v < target);
    }
    __syncthreads();
}

// ---------------- persistent bidirectional GRU layer (batch-split groups) ----------
// 4 independent sync groups (dir x batch-half), 24 CTAs each.  CTA owns 16 j-cols
// (48 gate rows) x 8 batches.  Whh slice bf16 hi/lo in SMEM B-layout; h exchanged
// via global bf16 hi/lo planes in A-fragment layout (8 real batch rows, 8 zero pad).
// Same warp K-split (2 chunks each) and reduction tree as the R4 kernel.
__global__ void __launch_bounds__(RT, 1) gru_layer_k(
    const float* __restrict__ Whh,   // [2][1152][384]
    const float* __restrict__ bhh,   // [2][1152]
    float* __restrict__ dout, int layer)
{
    extern __shared__ char smc[];
    __nv_bfloat16* Bs = (__nv_bfloat16*)smc;              // [2][12][48][40] = 92,160 B
    __nv_bfloat16* As = (__nv_bfloat16*)(smc + 92160);    // [2][12][16][40] = 30,720 B
    float*        red = (float*)(smc + 122880);           // [6][6][16][9]   = 20,736 B

    int tid = threadIdx.x, lane = tid & 31, w = tid >> 5;
    int bx  = blockIdx.x;
    int d   = bx / (2 * RNC);
    int rem = bx - d * 2 * RNC;
    int bh  = rem / RNC;
    int cid = rem - bh * RNC;
    int jb  = cid * RJ;
    unsigned* ctr = &g_ctr[layer][d][bh][0];

    // ---- prologue ----
    // zero As fully (pad batch rows 8..15 stay zero forever)
    for (int i = tid; i < 1920; i += RT) ((uint4*)As)[i] = make_uint4(0,0,0,0);
    // Whh slice -> Bs: rows n = g*16+jl (48), layout [plane][chunk12][n48][40]
    const float* W = Whh + (size_t)d * G3 * H_;
    for (int i = tid; i < 48 * H_; i += RT) {
        int n = i / H_;            // 0..47
        int k = i - n * H_;
        int g = n >> 4, jl = n & 15;
        float v = W[(size_t)(g * H_ + jb + jl) * H_ + k];
        __nv_bfloat16 hi = __float2bfloat16_rn(v);
        __nv_bfloat16 lo = __float2bfloat16_rn(v - __bfloat162float(hi));
        int addr = (k >> 5) * 1920 + n * 40 + (k & 31);
        Bs[addr]         = hi;
        Bs[23040 + addr] = lo;
    }
    // zero this group's phase-0 h planes (all 24 CTAs write zeros; benign race)
    {
        uint4* z = (uint4*)g_hA[d][bh][0];
        for (int i = tid; i < 960; i += RT) z[i] = make_uint4(0,0,0,0);
    }

    // gate-thread constants (tid<128: one (jl, b) output; 16 j x 8 b)
    int jl = tid >> 3, b = tid & 7;           // jl 0..15, b 0..7 (local)
    int j_g = jb + jl;
    int bg  = bh * 8 + b;                     // global batch
    float bhr = 0.f, bhz = 0.f, bhn = 0.f, hp = 0.f;
    if (tid < 128) {
        const float* bb = bhh + d * G3;
        bhr = bb[j_g]; bhz = bb[H_ + j_g]; bhn = bb[2 * H_ + j_g];
    }
    ctabar(ctr, RNC);

    unsigned sbase = (unsigned)__cvta_generic_to_shared(smc);
    unsigned Bb = sbase;
    unsigned Ab = sbase + 92160;
    unsigned a_off = (unsigned)((lane & 15) * 80 + ((lane >> 4) & 1) * 16);
    unsigned b_off = (unsigned)((((lane >> 4) & 1) * 8 + (lane & 7)) * 80 + ((lane >> 3) & 1) * 16);
    const float* xgbase = g_XG[d];

    for (int t = 0; t < S; t++) {
        int pos = d ? (S - 1 - t) : t;

        // copy h planes (15KB) global -> SMEM A rows 0..7 of each chunk
        {
            const uint4* src = (const uint4*)g_hA[d][bh][t & 1];
            uint4* dst = (uint4*)As;
#pragma unroll
            for (int i = 0; i < 5; i++) {
                int e   = tid + i * RT;        // 0..959
                int p   = e / 480;
                int rm  = e - p * 480;
                int c   = rm / 40;
                int rr  = rm - c * 40;
                dst[p * 960 + c * 80 + rr] = src[e];
            }
        }
        float xr = 0.f, xz = 0.f, xn = 0.f;
        if (tid < 128) {
            const float* xrow = xgbase + (size_t)(pos * B_ + bg) * G3;
            xr = xrow[j_g]; xz = xrow[H_ + j_g]; xn = xrow[2 * H_ + j_g];
        }
        __syncthreads();

        // tensor-core matvec: warp w handles k-chunks 2w, 2w+1 (64 k)
        float acc[6][4];
#pragma unroll
        for (int nt = 0; nt < 6; nt++)
#pragma unroll
            for (int q = 0; q < 4; q++) acc[nt][q] = 0.f;

#pragma unroll
        for (int cc = 0; cc < 2; cc++) {
            int ck = 2 * w + cc;
#pragma unroll
            for (int kk = 0; kk < 2; kk++) {
                unsigned ah[4], al[4], bhf[3][4], blf[3][4];
                unsigned ab = Ab + ck * 1280 + a_off + kk * 32;
                LDSM4(ah, ab);
                LDSM4(al, ab + 15360);
                unsigned bb2 = Bb + ck * 3840 + b_off + kk * 32;
#pragma unroll
                for (int np = 0; np < 3; np++) {
                    LDSM4(bhf[np], bb2 + np * 1280);
                    LDSM4(blf[np], bb2 + 46080 + np * 1280);
                }
#pragma unroll
                for (int nt = 0; nt < 6; nt++) {
                    int np = nt >> 1, sel = (nt & 1) * 2;
                    MMA16816(acc[nt], ah, &bhf[np][sel]);
                    MMA16816(acc[nt], ah, &blf[np][sel]);
                    MMA16816(acc[nt], al, &bhf[np][sel]);
                }
            }
        }
        // dump partials: red[w][nt][row(m)][col(n), pad 9]
        {
            int row = lane >> 2, colb = (lane & 3) * 2;
#pragma unroll
            for (int nt = 0; nt < 6; nt++) {
                float* rb = red + ((w * 6 + nt) * 16 + row) * 9 + colb;
                rb[0]  = acc[nt][0];
                rb[1]  = acc[nt][1];
                rb[72] = acc[nt][2];
                rb[73] = acc[nt][3];
            }
        }
        __syncthreads();

        // gate math + state update (128 threads)
        if (tid < 128) {
            int col = jl & 7;
            int nt0 = 0 * 2 + (jl >> 3);
            int nt1 = 1 * 2 + (jl >> 3);
            int nt2 = 2 * 2 + (jl >> 3);
            float sr = bhr, sz = bhz, sn = bhn;
#pragma unroll
            for (int ww = 0; ww < 6; ww++) {
                sr += red[((ww * 6 + nt0) * 16 + b) * 9 + col];
                sz += red[((ww * 6 + nt1) * 16 + b) * 9 + col];
                sn += red[((ww * 6 + nt2) * 16 + b) * 9 + col];
            }
            float rg = 1.f / (1.f + expf(-(xr + sr)));
            float zg = 1.f / (1.f + expf(-(xz + sz)));
            float ng = tanhf(xn + rg * sn);
            float hv = (1.f - zg) * ng + zg * hp;
            hp = hv;
            __nv_bfloat16 hi = __float2bfloat16_rn(hv);
            __nv_bfloat16 lo = __float2bfloat16_rn(hv - __bfloat162float(hi));
            int haddr = (j_g >> 5) * 320 + b * 40 + (j_g & 31);
            g_hA[d][bh][(t + 1) & 1][0][haddr] = hi;
            g_hA[d][bh][(t + 1) & 1][1][haddr] = lo;
            if (layer == 2)
                dout[((size_t)(bg * S + pos)) * D_ + d * H_ + j_g] = hv;
            else
                g_X[((size_t)(pos * B_ + bg)) * D_ + d * H_ + j_g] = hv;
        }

        if (t < S - 1) ctabar(ctr, (unsigned)RNC * (t + 2));
    }
}

// ---------------- launch ----------------
extern "C" void kernel_launch(void* const* d_in, const int* in_sizes, int n_in,
                              void* d_out, int out_size) {
    const float* x    = (const float*)d_in[0];
    const float* W_ih = (const float*)d_in[1];
    const float* W_hh = (const float*)d_in[2];
    const float* b_ih = (const float*)d_in[3];
    const float* b_hh = (const float*)d_in[4];
    float* out = (float*)d_out;

    int gsm = 92160 + 30720 + 20736;                  // 143,616 B
    cudaFuncSetAttribute(gru_layer_k, cudaFuncAttributeMaxDynamicSharedMemorySize, gsm);
    int msm = 2 * 4 * SMBLK * 2;                      // 81,920 B
    cudaFuncSetAttribute(gemm_xg_k, cudaFuncAttributeMaxDynamicSharedMemorySize, msm);

    patchify_k<<<49152, 256>>>(x);
    for (int l = 0; l < 3; l++) {
        dim3 gg(2304 / 128, 16384 / 128);   // (18,128)
        gemm_xg_k<<<gg, 256, msm>>>(W_ih + (size_t)l * 2 * G3 * D_,
                                    b_ih + (size_t)l * 2 * G3);
        gru_layer_k<<<2 * 2 * RNC, RT, gsm>>>(W_hh + (size_t)l * 2 * G3 * H_,
                                              b_hh + (size_t)l * 2 * G3,
                                              out, l);
    }
}